// round 1
// baseline (speedup 1.0000x reference)
#include <cuda_runtime.h>
#include <math_constants.h>

#define D_FEAT 128
#define K_NEIGH 32

// One CTA (128 threads = 4 warps) per batch item.
// Phase 1: stage center row in smem.
// Phase 2: each warp gathers 8 neighbor rows (coalesced float4), caches them in
//          smem, and computes dot(center, n) and ||n||^2 via fused warp reduce.
//          Ranking key = dot * rsqrt(||n||^2)  (center norm cancels for top-k).
// Phase 3: warp 0 does num_sample iterations of warp-argmax (ties -> lower idx).
// Phase 4: all 128 threads sum the selected smem rows columnwise, mean, relu.
__global__ __launch_bounds__(128, 8)
void intra_agg_kernel(const float* __restrict__ feats,
                      const int* __restrict__ nodes,
                      const int* __restrict__ neighs,
                      const int* __restrict__ nsamp_p,
                      float* __restrict__ out)
{
    __shared__ float s_neigh[K_NEIGH * D_FEAT];   // 16 KB neighbor row cache
    __shared__ float s_center[D_FEAT];
    __shared__ float s_sim[K_NEIGH];
    __shared__ int   s_sel[K_NEIGH];

    const int b    = blockIdx.x;
    const int tid  = threadIdx.x;
    const int warp = tid >> 5;
    const int lane = tid & 31;

    // ---- Phase 1: center row ----
    const int node = nodes[b];
    s_center[tid] = feats[(size_t)node * D_FEAT + tid];
    __syncthreads();
    const float4 c4 = reinterpret_cast<const float4*>(s_center)[lane];

    // ---- Phase 2: gather neighbors + similarity ----
    #pragma unroll
    for (int i = 0; i < K_NEIGH / 4; i++) {           // 8 rows per warp
        const int k    = warp * (K_NEIGH / 4) + i;
        const int nidx = neighs[b * K_NEIGH + k];
        const float4 v =
            reinterpret_cast<const float4*>(feats + (size_t)nidx * D_FEAT)[lane];
        reinterpret_cast<float4*>(s_neigh + k * D_FEAT)[lane] = v;

        float dot = v.x * c4.x + v.y * c4.y + v.z * c4.z + v.w * c4.w;
        float ss  = v.x * v.x  + v.y * v.y  + v.z * v.z  + v.w * v.w;
        #pragma unroll
        for (int off = 16; off; off >>= 1) {
            dot += __shfl_xor_sync(0xffffffffu, dot, off);
            ss  += __shfl_xor_sync(0xffffffffu, ss,  off);
        }
        if (lane == 0) s_sim[k] = dot * rsqrtf(ss);
    }
    __syncthreads();

    const int ns = nsamp_p ? *nsamp_p : 10;

    // ---- Phase 3: top-ns selection (warp 0) ----
    if (warp == 0) {
        float sim = s_sim[lane];
        for (int i = 0; i < ns; i++) {
            float v  = sim;
            int   idx = lane;
            #pragma unroll
            for (int off = 16; off; off >>= 1) {
                const float ov = __shfl_xor_sync(0xffffffffu, v,   off);
                const int   oi = __shfl_xor_sync(0xffffffffu, idx, off);
                if (ov > v || (ov == v && oi < idx)) { v = ov; idx = oi; }
            }
            if (lane == idx) sim = -CUDART_INF_F;     // remove winner
            if (lane == i)   s_sel[i] = idx;          // idx is uniform across warp
        }
    }
    __syncthreads();

    // ---- Phase 4: masked mean + relu ----
    float acc = 0.0f;
    for (int i = 0; i < ns; i++)
        acc += s_neigh[s_sel[i] * D_FEAT + tid];      // conflict-free: stride-1 in tid
    const float r = acc / (float)ns;
    out[(size_t)b * D_FEAT + tid] = r > 0.0f ? r : 0.0f;
}

extern "C" void kernel_launch(void* const* d_in, const int* in_sizes, int n_in,
                              void* d_out, int out_size)
{
    const float* feats  = (const float*)d_in[0];   // [N_NODES, 128] f32
    const int*   nodes  = (const int*)d_in[1];     // [B] i32
    const int*   neighs = (const int*)d_in[2];     // [B, 32] i32
    const int*   nsamp  = (n_in > 3) ? (const int*)d_in[3] : nullptr;  // scalar (10)

    const int B = in_sizes[1];                     // 32768
    intra_agg_kernel<<<B, 128>>>(feats, nodes, neighs, nsamp, (float*)d_out);
}

// round 2
// speedup vs baseline: 1.9798x; 1.9798x over previous
#include <cuda_runtime.h>
#include <math_constants.h>

#define D_FEAT   128
#define K_NEIGH  32
#define WARPS_PER_CTA 4

// Map float -> uint preserving order (monotone), so integer max == float max.
__device__ __forceinline__ unsigned order_key(float f) {
    unsigned x = __float_as_uint(f);
    return (x & 0x80000000u) ? ~x : (x | 0x80000000u);
}

// One WARP per batch item. No shared memory, no block syncs.
//  1. lane-wise coalesced load of the center row (float4 per lane).
//  2. lane k holds neighbor-index k; loop over the 32 rows: coalesced float4
//     gather + butterfly-reduced dot & sumsq; lane k keeps sim_k.
//     Ranking key = dot * rsqrt(||n||^2)  (center norm cancels for top-k).
//  3. num_sample rounds of exact warp argmax (reduce_max + ballot, tie -> lowest
//     index, matching jax.lax.top_k stability); winner's row is re-gathered from
//     global (L2/L1-hot) and accumulated into a per-lane float4.
//  4. mean + relu, coalesced float4 store.
__global__ __launch_bounds__(WARPS_PER_CTA * 32, 8)
void intra_agg_kernel(const float*  __restrict__ feats,
                      const int*    __restrict__ nodes,
                      const int*    __restrict__ neighs,
                      const int*    __restrict__ nsamp_p,
                      float*        __restrict__ out)
{
    const int lane = threadIdx.x & 31;
    const int warp = threadIdx.x >> 5;
    const int b    = blockIdx.x * WARPS_PER_CTA + warp;

    const float4* __restrict__ f4 = reinterpret_cast<const float4*>(feats);

    // ---- center row (warp-uniform row, coalesced 512B) ----
    const int node = nodes[b];
    const float4 c4 = f4[(size_t)node * (D_FEAT / 4) + lane];

    // ---- my neighbor index (one coalesced 128B load) ----
    const int my_idx = neighs[b * K_NEIGH + lane];

    // ---- similarities: lane k ends up holding sim of neighbor k ----
    float my_sim = 0.0f;
    #pragma unroll
    for (int k = 0; k < K_NEIGH; k++) {
        const int nidx = __shfl_sync(0xffffffffu, my_idx, k);
        const float4 v = f4[(size_t)nidx * (D_FEAT / 4) + lane];

        float dot = fmaf(v.x, c4.x, fmaf(v.y, c4.y, fmaf(v.z, c4.z, v.w * c4.w)));
        float ss  = fmaf(v.x, v.x,  fmaf(v.y, v.y,  fmaf(v.z, v.z,  v.w * v.w)));
        #pragma unroll
        for (int off = 16; off; off >>= 1) {
            dot += __shfl_xor_sync(0xffffffffu, dot, off);
            ss  += __shfl_xor_sync(0xffffffffu, ss,  off);
        }
        const float s = dot * rsqrtf(ss);
        if (lane == k) my_sim = s;
    }

    const int ns = nsamp_p ? *nsamp_p : 10;

    // ---- top-ns selection + accumulation of winner rows ----
    unsigned u = order_key(my_sim);
    float4 acc = make_float4(0.0f, 0.0f, 0.0f, 0.0f);
    for (int i = 0; i < ns; i++) {
        const unsigned m    = __reduce_max_sync(0xffffffffu, u);
        const unsigned mask = __ballot_sync(0xffffffffu, u == m);
        const int      w    = __ffs(mask) - 1;          // tie -> lowest index
        if (lane == w) u = 0u;                          // below order_key(-inf)

        const int nidx = __shfl_sync(0xffffffffu, my_idx, w);
        const float4 v = f4[(size_t)nidx * (D_FEAT / 4) + lane];
        acc.x += v.x; acc.y += v.y; acc.z += v.z; acc.w += v.w;
    }

    // ---- mean + relu, coalesced store ----
    const float inv = 1.0f / (float)ns;
    float4 r;
    r.x = fmaxf(acc.x * inv, 0.0f);
    r.y = fmaxf(acc.y * inv, 0.0f);
    r.z = fmaxf(acc.z * inv, 0.0f);
    r.w = fmaxf(acc.w * inv, 0.0f);
    reinterpret_cast<float4*>(out)[(size_t)b * (D_FEAT / 4) + lane] = r;
}

extern "C" void kernel_launch(void* const* d_in, const int* in_sizes, int n_in,
                              void* d_out, int out_size)
{
    const float* feats  = (const float*)d_in[0];   // [N_NODES, 128] f32
    const int*   nodes  = (const int*)d_in[1];     // [B] i32
    const int*   neighs = (const int*)d_in[2];     // [B, 32] i32
    const int*   nsamp  = (n_in > 3) ? (const int*)d_in[3] : nullptr;  // scalar (10)

    const int B = in_sizes[1];                     // 32768
    intra_agg_kernel<<<B / WARPS_PER_CTA, WARPS_PER_CTA * 32>>>(
        feats, nodes, neighs, nsamp, (float*)d_out);
}

// round 3
// speedup vs baseline: 2.8771x; 1.4532x over previous
#include <cuda_runtime.h>
#include <math_constants.h>

#define D_FEAT   128
#define K_NEIGH  32
#define WARPS_PER_CTA 4

// Map float -> uint preserving order (monotone), so integer max == float max.
__device__ __forceinline__ unsigned order_key(float f) {
    unsigned x = __float_as_uint(f);
    return (x & 0x80000000u) ? ~x : (x | 0x80000000u);
}

// One WARP per batch item, no shared memory.
// Similarity phase processes 4 neighbor rows per pass: the warp splits into
// 4 groups of 8 lanes, each group owns one row (each lane loads 16 floats of
// it), and the dot/sumsq reduction is a 3-stage butterfly over 8 lanes that
// serves all 4 rows with the SAME shuffle instructions (8 shuffles per 4 rows
// instead of 10+ per row). Shuffles ride the l1tex pipe, which ncu shows as
// the bottleneck, so cutting them ~5x is the point of this version.
// Ranking key = dot * rsqrt(||n||^2) (center norm cancels for top-k).
// Selection: exact warp argmax via order-preserving uint (tie -> lowest idx,
// matching jax.lax.top_k); winners re-gathered from global (L1/L2-hot).
__global__ __launch_bounds__(WARPS_PER_CTA * 32, 8)
void intra_agg_kernel(const float*  __restrict__ feats,
                      const int*    __restrict__ nodes,
                      const int*    __restrict__ neighs,
                      const int*    __restrict__ nsamp_p,
                      float*        __restrict__ out)
{
    const int lane = threadIdx.x & 31;
    const int warp = threadIdx.x >> 5;
    const int b    = blockIdx.x * WARPS_PER_CTA + warp;
    const int g    = lane >> 3;        // group 0..3  (which row of the quad)
    const int t    = lane & 7;         // lane within group

    const float4* __restrict__ f4 = reinterpret_cast<const float4*>(feats);

    // ---- center row: this lane's 16-float column slice (float4 idx t+8j) ----
    const int node = nodes[b];
    float4 c[4];
    #pragma unroll
    for (int j = 0; j < 4; j++)
        c[j] = f4[(size_t)node * (D_FEAT / 4) + t + 8 * j];

    // ---- my neighbor index (one coalesced 128B load) ----
    const int my_idx = neighs[b * K_NEIGH + lane];

    // ---- similarities: 8 passes x 4 rows; lane k ends with sim of row k ----
    float my_sim = 0.0f;
    #pragma unroll
    for (int p = 0; p < K_NEIGH / 4; p++) {
        const int nidx = __shfl_sync(0xffffffffu, my_idx, 4 * p + g);
        const float4* __restrict__ row = f4 + (size_t)nidx * (D_FEAT / 4);

        float dot = 0.0f, ss = 0.0f;
        #pragma unroll
        for (int j = 0; j < 4; j++) {
            const float4 v = row[t + 8 * j];
            dot = fmaf(v.x, c[j].x, fmaf(v.y, c[j].y,
                  fmaf(v.z, c[j].z, fmaf(v.w, c[j].w, dot))));
            ss  = fmaf(v.x, v.x, fmaf(v.y, v.y,
                  fmaf(v.z, v.z, fmaf(v.w, v.w, ss))));
        }
        // 3-stage butterfly within each 8-lane group (serves 4 rows at once)
        #pragma unroll
        for (int off = 1; off < 8; off <<= 1) {
            dot += __shfl_xor_sync(0xffffffffu, dot, off);
            ss  += __shfl_xor_sync(0xffffffffu, ss,  off);
        }
        const float s = dot * rsqrtf(ss);
        // route: row 4p+g' lives in group g' -> owner lane k = 4p+g'
        const float sv = __shfl_sync(0xffffffffu, s, (lane & 3) * 8);
        if ((lane >> 2) == p) my_sim = sv;
    }

    const int ns = nsamp_p ? *nsamp_p : 10;

    // ---- top-ns selection + accumulation of winner rows ----
    unsigned u = order_key(my_sim);
    float4 acc = make_float4(0.0f, 0.0f, 0.0f, 0.0f);
    for (int i = 0; i < ns; i++) {
        const unsigned m    = __reduce_max_sync(0xffffffffu, u);
        const unsigned mask = __ballot_sync(0xffffffffu, u == m);
        const int      w    = __ffs(mask) - 1;          // tie -> lowest index
        if (lane == w) u = 0u;                          // below any real key

        const int nidx = __shfl_sync(0xffffffffu, my_idx, w);
        const float4 v = f4[(size_t)nidx * (D_FEAT / 4) + lane];
        acc.x += v.x; acc.y += v.y; acc.z += v.z; acc.w += v.w;
    }

    // ---- mean + relu, coalesced store ----
    const float inv = 1.0f / (float)ns;
    float4 r;
    r.x = fmaxf(acc.x * inv, 0.0f);
    r.y = fmaxf(acc.y * inv, 0.0f);
    r.z = fmaxf(acc.z * inv, 0.0f);
    r.w = fmaxf(acc.w * inv, 0.0f);
    reinterpret_cast<float4*>(out)[(size_t)b * (D_FEAT / 4) + lane] = r;
}

extern "C" void kernel_launch(void* const* d_in, const int* in_sizes, int n_in,
                              void* d_out, int out_size)
{
    const float* feats  = (const float*)d_in[0];   // [N_NODES, 128] f32
    const int*   nodes  = (const int*)d_in[1];     // [B] i32
    const int*   neighs = (const int*)d_in[2];     // [B, 32] i32
    const int*   nsamp  = (n_in > 3) ? (const int*)d_in[3] : nullptr;  // scalar (10)

    const int B = in_sizes[1];                     // 32768
    intra_agg_kernel<<<B / WARPS_PER_CTA, WARPS_PER_CTA * 32>>>(
        feats, nodes, neighs, nsamp, (float*)d_out);
}